// round 11
// baseline (speedup 1.0000x reference)
#include <cuda_runtime.h>
#include <cstdint>

#define NN   50000
#define NE   500000
#define IND  128
#define HIDD 256
#define SCAN_B 512
#define NBLK ((NN + SCAN_B - 1) / SCAN_B)   // 98

// ---------------- scratch (static device globals) ---------------------------
__device__ float g_agg1[NN * IND];          // mean-agg of x
__device__ float g_h1  [NN * HIDD];         // layer-1 output
__device__ float g_agg2[NN * HIDD];         // mean-agg of h1
__device__ int   g_cnt [NN];
__device__ int   g_cur [NN];
__device__ int   g_off [NN];
__device__ int   g_csr [NE];
__device__ int   g_bsum [NBLK];
__device__ int   g_bpref[NBLK];
__device__ float g_wt1[2 * IND  * HIDD];    // [256][256]  (K', N) = [W1l; W1r]^T
__device__ float g_wt2[2 * HIDD * HIDD];    // [512][256]

// ---------------- weight transpose+concat (+ counter zeroing) ---------------
__global__ void k_wt1(const float* __restrict__ W1l, const float* __restrict__ W1r) {
    int idx = blockIdx.x * blockDim.x + threadIdx.x;
    if (idx < NN) { g_cnt[idx] = 0; g_cur[idx] = 0; }   // merged k_zero
    if (idx >= 2 * IND * HIDD) return;
    int k = idx / HIDD, j = idx % HIDD;
    g_wt1[idx] = (k < IND) ? W1l[j * IND + k] : W1r[j * IND + (k - IND)];
}
__global__ void k_wt2(const float* __restrict__ W2l, const float* __restrict__ W2r) {
    int idx = blockIdx.x * blockDim.x + threadIdx.x;
    if (idx >= 2 * HIDD * HIDD) return;
    int k = idx / HIDD, j = idx % HIDD;
    g_wt2[idx] = (k < HIDD) ? W2l[j * HIDD + k] : W2r[j * HIDD + (k - HIDD)];
}

// ---------------- CSR build --------------------------------------------------
__global__ void k_hist(const int* __restrict__ ei) {
    int e = blockIdx.x * blockDim.x + threadIdx.x;
    if (e < NE) {
        int d = ei[NE + e];
        if ((unsigned)d < NN) atomicAdd(&g_cnt[d], 1);
    }
}
__global__ void k_s1() {
    __shared__ int sm[SCAN_B];
    int i = blockIdx.x * SCAN_B + threadIdx.x;
    sm[threadIdx.x] = (i < NN) ? g_cnt[i] : 0;
    __syncthreads();
    for (int s = SCAN_B / 2; s > 0; s >>= 1) {
        if (threadIdx.x < s) sm[threadIdx.x] += sm[threadIdx.x + s];
        __syncthreads();
    }
    if (threadIdx.x == 0) g_bsum[blockIdx.x] = sm[0];
}
__global__ void k_s2() {            // 128-thread exclusive scan over NBLK=98
    __shared__ int sm[128];
    int t = threadIdx.x;
    int v = (t < NBLK) ? g_bsum[t] : 0;
    sm[t] = v;
    __syncthreads();
    for (int off = 1; off < 128; off <<= 1) {
        int u = (t >= off) ? sm[t - off] : 0;
        __syncthreads();
        sm[t] += u;
        __syncthreads();
    }
    if (t < NBLK) g_bpref[t] = sm[t] - v;   // exclusive
}
__global__ void k_s3() {
    __shared__ int sm[SCAN_B];
    int i = blockIdx.x * SCAN_B + threadIdx.x;
    int v = (i < NN) ? g_cnt[i] : 0;
    sm[threadIdx.x] = v;
    __syncthreads();
    for (int off = 1; off < SCAN_B; off <<= 1) {
        int t = (threadIdx.x >= off) ? sm[threadIdx.x - off] : 0;
        __syncthreads();
        sm[threadIdx.x] += t;
        __syncthreads();
    }
    if (i < NN) g_off[i] = g_bpref[blockIdx.x] + sm[threadIdx.x] - v;
}
__global__ void k_scatter(const int* __restrict__ ei) {
    int e = blockIdx.x * blockDim.x + threadIdx.x;
    if (e < NE) {
        int s = ei[e];
        int d = ei[NE + e];
        if ((unsigned)d < NN && (unsigned)s < NN) {
            int pos = atomicAdd(&g_cur[d], 1);
            g_csr[g_off[d] + pos] = s;
        }
    }
}

// ---------------- mean aggregation (warp per node, 4 edges in flight) -------
template <int D>
__device__ __forceinline__ void agg_body(const float* __restrict__ in,
                                         float* __restrict__ out) {
    int node = (blockIdx.x * blockDim.x + threadIdx.x) >> 5;
    int lane = threadIdx.x & 31;
    if (node >= NN) return;
    int beg = g_off[node];
    int c   = g_cnt[node];
    float4 a0 = make_float4(0.f, 0.f, 0.f, 0.f);
    float4 a1 = make_float4(0.f, 0.f, 0.f, 0.f);
    int j = 0;
    for (; j + 3 < c; j += 4) {
        int s0 = g_csr[beg + j];
        int s1 = g_csr[beg + j + 1];
        int s2 = g_csr[beg + j + 2];
        int s3 = g_csr[beg + j + 3];
        const float4* r0 = (const float4*)(in + (size_t)s0 * D);
        const float4* r1 = (const float4*)(in + (size_t)s1 * D);
        const float4* r2 = (const float4*)(in + (size_t)s2 * D);
        const float4* r3 = (const float4*)(in + (size_t)s3 * D);
        float4 v0 = r0[lane];
        float4 v1 = r1[lane];
        float4 v2 = r2[lane];
        float4 v3 = r3[lane];
        a0.x += (v0.x + v1.x) + (v2.x + v3.x);
        a0.y += (v0.y + v1.y) + (v2.y + v3.y);
        a0.z += (v0.z + v1.z) + (v2.z + v3.z);
        a0.w += (v0.w + v1.w) + (v2.w + v3.w);
        if (D == 256) {
            float4 w0 = r0[lane + 32];
            float4 w1 = r1[lane + 32];
            float4 w2 = r2[lane + 32];
            float4 w3 = r3[lane + 32];
            a1.x += (w0.x + w1.x) + (w2.x + w3.x);
            a1.y += (w0.y + w1.y) + (w2.y + w3.y);
            a1.z += (w0.z + w1.z) + (w2.z + w3.z);
            a1.w += (w0.w + w1.w) + (w2.w + w3.w);
        }
    }
    for (; j < c; j++) {
        int s = g_csr[beg + j];
        const float4* r = (const float4*)(in + (size_t)s * D);
        float4 v = r[lane];
        a0.x += v.x; a0.y += v.y; a0.z += v.z; a0.w += v.w;
        if (D == 256) {
            float4 w = r[lane + 32];
            a1.x += w.x; a1.y += w.y; a1.z += w.z; a1.w += w.w;
        }
    }
    float inv = (c > 0) ? 1.0f / (float)c : 0.0f;
    float4* o = (float4*)(out + (size_t)node * D);
    o[lane] = make_float4(a0.x * inv, a0.y * inv, a0.z * inv, a0.w * inv);
    if (D == 256)
        o[lane + 32] = make_float4(a1.x * inv, a1.y * inv, a1.z * inv, a1.w * inv);
}
__global__ void k_agg1(const float* __restrict__ x) { agg_body<IND >(x,    g_agg1); }
__global__ void k_agg2()                            { agg_body<HIDD>(g_h1, g_agg2); }

// ---------------- fused GEMM (double-buffered; R9 inner loop) ---------------
// C = relu([A1|A2] @ Wt + bias). 128x128 tile, BK=16, 256 thr, 8x8 microtile.
template <int KH>
__device__ __forceinline__ void gemm_body(const float* __restrict__ A1,
                                          const float* __restrict__ A2,
                                          const float* __restrict__ Wt,
                                          const float* __restrict__ bias,
                                          float* __restrict__ C) {
    constexpr int BM = 128, BN = 128, BK = 16, KK = 2 * KH;
    constexpr int NCH = KK / BK;
    __shared__ float As[2][BK][BM];
    __shared__ float Bs[2][BK][BN];
    int tid   = threadIdx.x;          // 256 threads
    int mBase = blockIdx.y * BM;
    int nBase = blockIdx.x * BN;
    int tm = tid >> 4, tn = tid & 15; // 16 x 16 threads, 8x8 microtile

    int aRow0 = (tid + 0)   >> 2, aC40 = (tid + 0)   & 3;
    int aRow1 = (tid + 256) >> 2, aC41 = (tid + 256) & 3;
    int bKr0  = (tid + 0)   >> 5, bCc0 = ((tid + 0)   & 31) << 2;
    int bKr1  = (tid + 256) >> 5, bCc1 = ((tid + 256) & 31) << 2;

    float acc[8][8];
    #pragma unroll
    for (int i = 0; i < 8; i++)
        #pragma unroll
        for (int j = 0; j < 8; j++) acc[i][j] = 0.f;

    float4 avA0, avA1, avB0, avB1;
    auto load_tile = [&](int kbase) {
        const float* src = (kbase < KH) ? A1 : A2;
        int col = (kbase < KH) ? kbase : kbase - KH;
        int m0 = mBase + aRow0;
        int m1 = mBase + aRow1;
        avA0 = make_float4(0.f, 0.f, 0.f, 0.f);
        avA1 = make_float4(0.f, 0.f, 0.f, 0.f);
        if (m0 < NN) avA0 = *(const float4*)(src + (size_t)m0 * KH + col + aC40 * 4);
        if (m1 < NN) avA1 = *(const float4*)(src + (size_t)m1 * KH + col + aC41 * 4);
        avB0 = *(const float4*)(Wt + (size_t)(kbase + bKr0) * HIDD + nBase + bCc0);
        avB1 = *(const float4*)(Wt + (size_t)(kbase + bKr1) * HIDD + nBase + bCc1);
    };
    auto store_tile = [&](int buf) {
        As[buf][aC40 * 4 + 0][aRow0] = avA0.x;
        As[buf][aC40 * 4 + 1][aRow0] = avA0.y;
        As[buf][aC40 * 4 + 2][aRow0] = avA0.z;
        As[buf][aC40 * 4 + 3][aRow0] = avA0.w;
        As[buf][aC41 * 4 + 0][aRow1] = avA1.x;
        As[buf][aC41 * 4 + 1][aRow1] = avA1.y;
        As[buf][aC41 * 4 + 2][aRow1] = avA1.z;
        As[buf][aC41 * 4 + 3][aRow1] = avA1.w;
        *(float4*)&Bs[buf][bKr0][bCc0] = avB0;
        *(float4*)&Bs[buf][bKr1][bCc1] = avB1;
    };

    load_tile(0);
    store_tile(0);
    __syncthreads();

    for (int ch = 0; ch < NCH; ch++) {
        int cur = ch & 1;
        if (ch + 1 < NCH) load_tile((ch + 1) * BK);

        #pragma unroll
        for (int k = 0; k < BK; k++) {
            float ra[8], rb[8];
            #pragma unroll
            for (int i = 0; i < 8; i++) ra[i] = As[cur][k][tm * 8 + i];
            #pragma unroll
            for (int j = 0; j < 8; j++) rb[j] = Bs[cur][k][tn * 8 + j];
            #pragma unroll
            for (int i = 0; i < 8; i++)
                #pragma unroll
                for (int j = 0; j < 8; j++) acc[i][j] += ra[i] * rb[j];
        }

        if (ch + 1 < NCH) {
            store_tile(cur ^ 1);
            __syncthreads();
        }
    }

    // ---- epilogue: bias + relu, vector stores ----
    float4 bv0 = *(const float4*)(bias + nBase + tn * 8);
    float4 bv1 = *(const float4*)(bias + nBase + tn * 8 + 4);
    #pragma unroll
    for (int i = 0; i < 8; i++) {
        int m = mBase + tm * 8 + i;
        if (m >= NN) continue;
        float4 o0, o1;
        o0.x = fmaxf(acc[i][0] + bv0.x, 0.f);
        o0.y = fmaxf(acc[i][1] + bv0.y, 0.f);
        o0.z = fmaxf(acc[i][2] + bv0.z, 0.f);
        o0.w = fmaxf(acc[i][3] + bv0.w, 0.f);
        o1.x = fmaxf(acc[i][4] + bv1.x, 0.f);
        o1.y = fmaxf(acc[i][5] + bv1.y, 0.f);
        o1.z = fmaxf(acc[i][6] + bv1.z, 0.f);
        o1.w = fmaxf(acc[i][7] + bv1.w, 0.f);
        float4* d = (float4*)(C + (size_t)m * HIDD + nBase + tn * 8);
        d[0] = o0;
        d[1] = o1;
    }
}

__global__ void k_gemm1(const float* __restrict__ x, const float* __restrict__ b1) {
    gemm_body<IND>(g_agg1, x, g_wt1, b1, g_h1);
}
__global__ void k_gemm2(const float* __restrict__ b2, float* __restrict__ out) {
    gemm_body<HIDD>(g_agg2, g_h1, g_wt2, b2, out);
}

// ---------------- launch -----------------------------------------------------
extern "C" void kernel_launch(void* const* d_in, const int* in_sizes, int n_in,
                              void* d_out, int out_size) {
    const float* x   = (const float*)d_in[0];
    const int*   ei  = (const int*)d_in[1];      // int32 (JAX default x64-disabled)
    const float* W1l = (const float*)d_in[2];
    const float* b1l = (const float*)d_in[3];
    const float* W1r = (const float*)d_in[4];
    const float* W2l = (const float*)d_in[5];
    const float* b2l = (const float*)d_in[6];
    const float* W2r = (const float*)d_in[7];
    float* out = (float*)d_out;

    // weights -> concatenated/transposed layout (k_wt1 also zeroes counters)
    k_wt1<<<(2 * IND * HIDD + 255) / 256, 256>>>(W1l, W1r);
    k_wt2<<<(2 * HIDD * HIDD + 255) / 256, 256>>>(W2l, W2r);

    // CSR build (by destination)
    k_hist<<<(NE + 255) / 256, 256>>>(ei);
    k_s1<<<NBLK, SCAN_B>>>();
    k_s2<<<1, 128>>>();
    k_s3<<<NBLK, SCAN_B>>>();
    k_scatter<<<(NE + 255) / 256, 256>>>(ei);

    dim3 grid(HIDD / 128, (NN + 127) / 128);   // 2 x 391

    // layer 1: mean-agg(x) then fused dual-GEMM + bias + relu
    k_agg1<<<(NN + 7) / 8, 256>>>(x);
    k_gemm1<<<grid, 256>>>(x, b1l);

    // layer 2
    k_agg2<<<(NN + 7) / 8, 256>>>();
    k_gemm2<<<grid, 256>>>(b2l, out);
}

// round 14
// speedup vs baseline: 1.0830x; 1.0830x over previous
#include <cuda_runtime.h>
#include <cstdint>

#define NN   50000
#define NE   500000
#define IND  128
#define HIDD 256
#define SCAN_B 512
#define NBLK ((NN + SCAN_B - 1) / SCAN_B)   // 98

// ---------------- scratch (static device globals) ---------------------------
__device__ float g_agg1[NN * IND];          // mean-agg of x
__device__ float g_h1  [NN * HIDD];         // layer-1 output
__device__ float g_agg2[NN * HIDD];         // mean-agg of h1
__device__ int   g_cnt [NN];
__device__ int   g_cur [NN];
__device__ int   g_off [NN];
__device__ int   g_csr [NE];
__device__ int   g_bsum [NBLK];
__device__ int   g_bpref[NBLK];
__device__ float g_wt1[2 * IND  * HIDD];    // [256][256]  (K', N) = [W1l; W1r]^T
__device__ float g_wt2[2 * HIDD * HIDD];    // [512][256]

// ---------------- weight transpose+concat (+ counter zeroing) ---------------
__global__ void k_wt1(const float* __restrict__ W1l, const float* __restrict__ W1r) {
    int idx = blockIdx.x * blockDim.x + threadIdx.x;
    if (idx < NN) { g_cnt[idx] = 0; g_cur[idx] = 0; }   // merged k_zero
    if (idx >= 2 * IND * HIDD) return;
    int k = idx / HIDD, j = idx % HIDD;
    g_wt1[idx] = (k < IND) ? W1l[j * IND + k] : W1r[j * IND + (k - IND)];
}
__global__ void k_wt2(const float* __restrict__ W2l, const float* __restrict__ W2r) {
    int idx = blockIdx.x * blockDim.x + threadIdx.x;
    if (idx >= 2 * HIDD * HIDD) return;
    int k = idx / HIDD, j = idx % HIDD;
    g_wt2[idx] = (k < HIDD) ? W2l[j * HIDD + k] : W2r[j * HIDD + (k - HIDD)];
}

// ---------------- CSR build --------------------------------------------------
__global__ void k_hist(const int* __restrict__ ei) {
    int e = blockIdx.x * blockDim.x + threadIdx.x;
    if (e < NE) {
        int d = ei[NE + e];
        if ((unsigned)d < NN) atomicAdd(&g_cnt[d], 1);
    }
}
__global__ void k_s1() {
    __shared__ int sm[SCAN_B];
    int i = blockIdx.x * SCAN_B + threadIdx.x;
    sm[threadIdx.x] = (i < NN) ? g_cnt[i] : 0;
    __syncthreads();
    for (int s = SCAN_B / 2; s > 0; s >>= 1) {
        if (threadIdx.x < s) sm[threadIdx.x] += sm[threadIdx.x + s];
        __syncthreads();
    }
    if (threadIdx.x == 0) g_bsum[blockIdx.x] = sm[0];
}
__global__ void k_s2() {            // 128-thread exclusive scan over NBLK=98
    __shared__ int sm[128];
    int t = threadIdx.x;
    int v = (t < NBLK) ? g_bsum[t] : 0;
    sm[t] = v;
    __syncthreads();
    for (int off = 1; off < 128; off <<= 1) {
        int u = (t >= off) ? sm[t - off] : 0;
        __syncthreads();
        sm[t] += u;
        __syncthreads();
    }
    if (t < NBLK) g_bpref[t] = sm[t] - v;   // exclusive
}
__global__ void k_s3() {
    __shared__ int sm[SCAN_B];
    int i = blockIdx.x * SCAN_B + threadIdx.x;
    int v = (i < NN) ? g_cnt[i] : 0;
    sm[threadIdx.x] = v;
    __syncthreads();
    for (int off = 1; off < SCAN_B; off <<= 1) {
        int t = (threadIdx.x >= off) ? sm[threadIdx.x - off] : 0;
        __syncthreads();
        sm[threadIdx.x] += t;
        __syncthreads();
    }
    if (i < NN) g_off[i] = g_bpref[blockIdx.x] + sm[threadIdx.x] - v;
}
__global__ void k_scatter(const int* __restrict__ ei) {
    int e = blockIdx.x * blockDim.x + threadIdx.x;
    if (e < NE) {
        int s = ei[e];
        int d = ei[NE + e];
        if ((unsigned)d < NN && (unsigned)s < NN) {
            int pos = atomicAdd(&g_cur[d], 1);
            g_csr[g_off[d] + pos] = s;
        }
    }
}

// ---------------- mean aggregation (warp per node, 2 edges in flight) -------
template <int D>
__device__ __forceinline__ void agg_body(const float* __restrict__ in,
                                         float* __restrict__ out) {
    int node = (blockIdx.x * blockDim.x + threadIdx.x) >> 5;
    int lane = threadIdx.x & 31;
    if (node >= NN) return;
    int beg = g_off[node];
    int c   = g_cnt[node];
    float4 a0 = make_float4(0.f, 0.f, 0.f, 0.f);
    float4 a1 = make_float4(0.f, 0.f, 0.f, 0.f);
    int j = 0;
    for (; j + 1 < c; j += 2) {
        int s0 = g_csr[beg + j];
        int s1 = g_csr[beg + j + 1];
        const float4* r0 = (const float4*)(in + (size_t)s0 * D);
        const float4* r1 = (const float4*)(in + (size_t)s1 * D);
        float4 v0 = r0[lane];
        float4 v1 = r1[lane];
        if (D == 256) {
            float4 w0 = r0[lane + 32];
            float4 w1 = r1[lane + 32];
            a1.x += w0.x + w1.x; a1.y += w0.y + w1.y;
            a1.z += w0.z + w1.z; a1.w += w0.w + w1.w;
        }
        a0.x += v0.x + v1.x; a0.y += v0.y + v1.y;
        a0.z += v0.z + v1.z; a0.w += v0.w + v1.w;
    }
    if (j < c) {
        int s = g_csr[beg + j];
        const float4* r = (const float4*)(in + (size_t)s * D);
        float4 v = r[lane];
        a0.x += v.x; a0.y += v.y; a0.z += v.z; a0.w += v.w;
        if (D == 256) {
            float4 w = r[lane + 32];
            a1.x += w.x; a1.y += w.y; a1.z += w.z; a1.w += w.w;
        }
    }
    float inv = (c > 0) ? 1.0f / (float)c : 0.0f;
    float4* o = (float4*)(out + (size_t)node * D);
    o[lane] = make_float4(a0.x * inv, a0.y * inv, a0.z * inv, a0.w * inv);
    if (D == 256)
        o[lane + 32] = make_float4(a1.x * inv, a1.y * inv, a1.z * inv, a1.w * inv);
}
__global__ void k_agg1(const float* __restrict__ x) { agg_body<IND >(x,    g_agg1); }
__global__ void k_agg2()                            { agg_body<HIDD>(g_h1, g_agg2); }

// ---------------- fused GEMM (double-buffered, LDS.128, no temp arrays) -----
// C = relu([A1|A2] @ Wt + bias). 128x128 tile, BK=16, 256 thr, 8x8 microtile.
template <int KH>
__device__ __forceinline__ void gemm_body(const float* __restrict__ A1,
                                          const float* __restrict__ A2,
                                          const float* __restrict__ Wt,
                                          const float* __restrict__ bias,
                                          float* __restrict__ C) {
    constexpr int BM = 128, BN = 128, BK = 16, KK = 2 * KH;
    constexpr int NCH = KK / BK;
    __shared__ __align__(16) float As[2][BK][BM];
    __shared__ __align__(16) float Bs[2][BK][BN];
    int tid   = threadIdx.x;          // 256 threads
    int mBase = blockIdx.y * BM;
    int nBase = blockIdx.x * BN;
    int tm = tid >> 4, tn = tid & 15; // 16 x 16 threads, 8x8 microtile

    int aRow0 = (tid + 0)   >> 2, aC40 = (tid + 0)   & 3;
    int aRow1 = (tid + 256) >> 2, aC41 = (tid + 256) & 3;
    int bKr0  = (tid + 0)   >> 5, bCc0 = ((tid + 0)   & 31) << 2;
    int bKr1  = (tid + 256) >> 5, bCc1 = ((tid + 256) & 31) << 2;

    float acc[8][8];
    #pragma unroll
    for (int i = 0; i < 8; i++)
        #pragma unroll
        for (int j = 0; j < 8; j++) acc[i][j] = 0.f;

    float4 avA0, avA1, avB0, avB1;
    auto load_tile = [&](int kbase) {
        const float* src = (kbase < KH) ? A1 : A2;
        int col = (kbase < KH) ? kbase : kbase - KH;
        int m0 = mBase + aRow0;
        int m1 = mBase + aRow1;
        avA0 = make_float4(0.f, 0.f, 0.f, 0.f);
        avA1 = make_float4(0.f, 0.f, 0.f, 0.f);
        if (m0 < NN) avA0 = *(const float4*)(src + (size_t)m0 * KH + col + aC40 * 4);
        if (m1 < NN) avA1 = *(const float4*)(src + (size_t)m1 * KH + col + aC41 * 4);
        avB0 = *(const float4*)(Wt + (size_t)(kbase + bKr0) * HIDD + nBase + bCc0);
        avB1 = *(const float4*)(Wt + (size_t)(kbase + bKr1) * HIDD + nBase + bCc1);
    };
    auto store_tile = [&](int buf) {
        As[buf][aC40 * 4 + 0][aRow0] = avA0.x;
        As[buf][aC40 * 4 + 1][aRow0] = avA0.y;
        As[buf][aC40 * 4 + 2][aRow0] = avA0.z;
        As[buf][aC40 * 4 + 3][aRow0] = avA0.w;
        As[buf][aC41 * 4 + 0][aRow1] = avA1.x;
        As[buf][aC41 * 4 + 1][aRow1] = avA1.y;
        As[buf][aC41 * 4 + 2][aRow1] = avA1.z;
        As[buf][aC41 * 4 + 3][aRow1] = avA1.w;
        *(float4*)&Bs[buf][bKr0][bCc0] = avB0;
        *(float4*)&Bs[buf][bKr1][bCc1] = avB1;
    };

    load_tile(0);
    store_tile(0);
    __syncthreads();

// 8 FMAs against one A scalar, direct float4 fields (no temp arrays -> no MOVs)
#define FMAROW(i, a)                                                           \
    acc[i][0] += (a) * rb0.x; acc[i][1] += (a) * rb0.y;                        \
    acc[i][2] += (a) * rb0.z; acc[i][3] += (a) * rb0.w;                        \
    acc[i][4] += (a) * rb1.x; acc[i][5] += (a) * rb1.y;                        \
    acc[i][6] += (a) * rb1.z; acc[i][7] += (a) * rb1.w;

    for (int ch = 0; ch < NCH; ch++) {
        int cur = ch & 1;
        if (ch + 1 < NCH) load_tile((ch + 1) * BK);

        const float* Ap = &As[cur][0][tm * 8];
        const float* Bp = &Bs[cur][0][tn * 8];
        #pragma unroll
        for (int k = 0; k < BK; k++) {
            float4 ra0 = *(const float4*)(Ap + k * BM);      // LDS.128 x4
            float4 ra1 = *(const float4*)(Ap + k * BM + 4);
            float4 rb0 = *(const float4*)(Bp + k * BN);
            float4 rb1 = *(const float4*)(Bp + k * BN + 4);
            FMAROW(0, ra0.x) FMAROW(1, ra0.y) FMAROW(2, ra0.z) FMAROW(3, ra0.w)
            FMAROW(4, ra1.x) FMAROW(5, ra1.y) FMAROW(6, ra1.z) FMAROW(7, ra1.w)
        }

        if (ch + 1 < NCH) {
            store_tile(cur ^ 1);
            __syncthreads();
        }
    }
#undef FMAROW

    // ---- epilogue: bias + relu (R9 form) ----
    #pragma unroll
    for (int i = 0; i < 8; i++) {
        int m = mBase + tm * 8 + i;
        if (m >= NN) continue;
        #pragma unroll
        for (int j = 0; j < 8; j++) {
            int n = nBase + tn * 8 + j;
            float v = acc[i][j] + bias[n];
            C[(size_t)m * HIDD + n] = fmaxf(v, 0.0f);
        }
    }
}

__global__ void k_gemm1(const float* __restrict__ x, const float* __restrict__ b1) {
    gemm_body<IND>(g_agg1, x, g_wt1, b1, g_h1);
}
__global__ void k_gemm2(const float* __restrict__ b2, float* __restrict__ out) {
    gemm_body<HIDD>(g_agg2, g_h1, g_wt2, b2, out);
}

// ---------------- launch -----------------------------------------------------
extern "C" void kernel_launch(void* const* d_in, const int* in_sizes, int n_in,
                              void* d_out, int out_size) {
    const float* x   = (const float*)d_in[0];
    const int*   ei  = (const int*)d_in[1];      // int32 (JAX default x64-disabled)
    const float* W1l = (const float*)d_in[2];
    const float* b1l = (const float*)d_in[3];
    const float* W1r = (const float*)d_in[4];
    const float* W2l = (const float*)d_in[5];
    const float* b2l = (const float*)d_in[6];
    const float* W2r = (const float*)d_in[7];
    float* out = (float*)d_out;

    // weights -> concatenated/transposed layout (k_wt1 also zeroes counters)
    k_wt1<<<(2 * IND * HIDD + 255) / 256, 256>>>(W1l, W1r);
    k_wt2<<<(2 * HIDD * HIDD + 255) / 256, 256>>>(W2l, W2r);

    // CSR build (by destination)
    k_hist<<<(NE + 255) / 256, 256>>>(ei);
    k_s1<<<NBLK, SCAN_B>>>();
    k_s2<<<1, 128>>>();
    k_s3<<<NBLK, SCAN_B>>>();
    k_scatter<<<(NE + 255) / 256, 256>>>(ei);

    dim3 grid(HIDD / 128, (NN + 127) / 128);   // 2 x 391

    // layer 1: mean-agg(x) then fused dual-GEMM + bias + relu
    k_agg1<<<(NN + 7) / 8, 256>>>(x);
    k_gemm1<<<grid, 256>>>(x, b1l);

    // layer 2
    k_agg2<<<(NN + 7) / 8, 256>>>();
    k_gemm2<<<grid, 256>>>(b2l, out);
}